// round 9
// baseline (speedup 1.0000x reference)
#include <cuda_runtime.h>
#include <cstdint>

// GRU B=64,T=4096,F=100,H=200,O=1. 32 clusters x 4 CTAs, 320 thr.
// Phase A: CTA-private gx = x·Wi -> scratch (verified).
// Phase B: recurrence with BATCH-STAGGERED phases: two mbarriers (one per batch,
//   count=4); each batch's rendezvous latency hides under the other batch's
//   dot+epilogue; only warp 9 ever polls a barrier. Wh register-resident
//   (104 regs/thread, K-half split); h via DSMEM pushes; hnew -> g_h scratch.
// Phase C: y = h·Wo + bo GEMV (measured 47us).

#define Bq      64
#define Tq      4096
#define Fq      100
#define Hq      200
#define G3      600
#define BT      (Bq * Tq)
#define CLUSTER 4
#define BG      2
#define JPC     50
#define NTHR    320
#define KHH     104
#define TT      32
#define GRID    128

__device__ float g_gx[(size_t)GRID * Tq * BG * 160];   // CTA-private [t][b][160]
__device__ float g_h [(size_t)BT * Hq];                // [row=b*Tq+t][200]

__device__ __forceinline__ uint32_t smem_u32(const void* p) {
    return (uint32_t)__cvta_generic_to_shared(p);
}
__device__ __forceinline__ void st_cluster_f32(uint32_t laddr, uint32_t rr, float v) {
    uint32_t ra;
    asm volatile("mapa.shared::cluster.u32 %0, %1, %2;" : "=r"(ra) : "r"(laddr), "r"(rr));
    asm volatile("st.shared::cluster.f32 [%0], %1;" :: "r"(ra), "f"(v) : "memory");
}
__device__ __forceinline__ void mbar_init(uint32_t a, uint32_t cnt) {
    asm volatile("mbarrier.init.shared.b64 [%0], %1;" :: "r"(a), "r"(cnt) : "memory");
}
__device__ __forceinline__ void mbar_arrive_cluster(uint32_t local_a, uint32_t rr) {
    asm volatile(
        "{\n\t.reg .b32 ra;\n\t"
        "mapa.shared::cluster.u32 ra, %0, %1;\n\t"
        "mbarrier.arrive.release.cluster.shared::cluster.b64 _, [ra];\n\t}"
        :: "r"(local_a), "r"(rr) : "memory");
}
__device__ __forceinline__ void mbar_wait(uint32_t a, uint32_t parity) {
    asm volatile(
        "{\n\t.reg .pred P;\n\t"
        "WL_%=:\n\t"
        "mbarrier.try_wait.parity.acquire.cluster.shared::cta.b64 P, [%0], %1, 0x989680;\n\t"
        "@P bra.uni WD_%=;\n\t"
        "bra.uni WL_%=;\n\t"
        "WD_%=:\n\t}"
        :: "r"(a), "r"(parity) : "memory");
}
__device__ __forceinline__ void ffma2(unsigned long long& acc,
                                      unsigned long long a, unsigned long long b) {
    asm("fma.rn.f32x2 %0, %1, %2, %0;" : "+l"(acc) : "l"(a), "l"(b));
}
__device__ __forceinline__ float fold2(unsigned long long a, unsigned long long b) {
    unsigned long long s;
    asm("add.rn.f32x2 %0, %1, %2;" : "=l"(s) : "l"(a), "l"(b));
    return __uint_as_float((unsigned)s) + __uint_as_float((unsigned)(s >> 32));
}
__device__ __forceinline__ unsigned long long pack2(float a, float b) {
    return (unsigned long long)__float_as_uint(a) |
           ((unsigned long long)__float_as_uint(b) << 32);
}
__device__ __forceinline__ float sigf(float x) {
    return __fdividef(1.0f, 1.0f + __expf(-x));
}
__device__ __forceinline__ float tanh_fast(float x) {
    return 2.0f * sigf(2.0f * x) - 1.0f;
}

struct __align__(16) Smem {
    float h[2][BG][208];            // parity, batch (pads zeroed)
    float gh[2][BG][160];           // K-half partials [kh][b][col]
    float xs[BG][TT][104];          // phase-A staging (pads zeroed)
    unsigned long long mbar[2];     // one per batch
};

__global__ void __launch_bounds__(NTHR, 1)
gru_kernel(const float* __restrict__ x,  const float* __restrict__ Wi,
           const float* __restrict__ bi, const float* __restrict__ Wh,
           const float* __restrict__ bhn)
{
    extern __shared__ char smraw[];
    Smem* sm = reinterpret_cast<Smem*>(smraw);
    const int tid = threadIdx.x;
    uint32_t rank;
    asm("mov.u32 %0, %%cluster_ctarank;" : "=r"(rank));
    const int b0g = (blockIdx.x >> 2) * BG;
    float* gsl = &g_gx[(size_t)blockIdx.x * Tq * (BG * 160)];
    const uint32_t mb0 = smem_u32(&sm->mbar[0]);
    const uint32_t mb1 = smem_u32(&sm->mbar[1]);

    // ---- one-time SMEM init ----
    for (int i = tid; i < 2 * BG * 208; i += NTHR)
        (&sm->h[0][0][0])[i] = 0.f;
    for (int i = tid; i < BG * TT * 4; i += NTHR) {
        int b2 = i / (TT * 4), rem = i - b2 * (TT * 4);
        sm->xs[b2][rem >> 2][100 + (rem & 3)] = 0.f;
    }
    if (tid == 0) { mbar_init(mb0, CLUSTER); mbar_init(mb1, CLUSTER); }
    __syncthreads();

    // ================= Phase A: gx = x · Wi (CTA-private slice) =================
    {
        const int c   = tid >> 1;        // 0..159 (c<150 real)
        const int b   = tid & 1;
        const bool act = (c < 150);
        int gcol = 0;
        if (act) { int g = c / JPC, j2 = c - g * JPC; gcol = g * Hq + (int)rank * JPC + j2; }

        ulonglong2 wr[26];               // k = 0..103 (100 real + 4 zero pad)
        #pragma unroll
        for (int q = 0; q < 26; ++q) {
            float v[4];
            #pragma unroll
            for (int r = 0; r < 4; ++r) {
                int k = q * 4 + r;
                v[r] = (act && k < Fq) ? Wi[(size_t)k * G3 + gcol] : 0.f;
            }
            wr[q].x = pack2(v[0], v[1]);
            wr[q].y = pack2(v[2], v[3]);
        }

        for (int t0 = 0; t0 < Tq; t0 += TT) {
            __syncthreads();
            for (int i = tid; i < BG * TT * Fq; i += NTHR) {
                int b2 = i / (TT * Fq), rem = i - b2 * (TT * Fq);
                int r = rem / Fq, f = rem - r * Fq;
                sm->xs[b2][r][f] =
                    x[(size_t)(b0g + b2) * (Tq * Fq) + (size_t)(t0 + r) * Fq + f];
            }
            __syncthreads();
            if (act) {
                for (int r = 0; r < TT; ++r) {
                    const ulonglong2* vp = reinterpret_cast<const ulonglong2*>(sm->xs[b][r]);
                    unsigned long long a0 = 0, a1 = 0;
                    #pragma unroll
                    for (int q = 0; q < 26; ++q) {
                        ulonglong2 v = vp[q];
                        ffma2(a0, wr[q].x, v.x);
                        ffma2(a1, wr[q].y, v.y);
                    }
                    gsl[(size_t)(t0 + r) * (BG * 160) + b * 160 + c] = fold2(a0, a1);
                }
            }
        }
    }
    __syncthreads();   // gsl visible CTA-wide

    // ================= Phase B: recurrence (batch-staggered) =================
    const int wid  = tid >> 5, lane = tid & 31;
    const int kh   = (wid >= 5);
    const int col  = (kh ? wid - 5 : wid) * 32 + lane;   // 0..159 (150 real)

    // register-resident Wh: column col, K-half slice (104 floats = 52 packed)
    ulonglong2 wreg[26];
    {
        int gcol = 0;
        const bool real = (col < 150);
        if (real) {
            int g = col / JPC, jj2 = col - g * JPC;
            gcol = g * Hq + (int)rank * JPC + jj2;
        }
        #pragma unroll
        for (int q = 0; q < 26; ++q) {
            float v[4];
            #pragma unroll
            for (int r = 0; r < 4; ++r) {
                int k = kh * KHH + q * 4 + r;
                v[r] = (real && k < Hq) ? Wh[(size_t)k * G3 + gcol] : 0.f;
            }
            wreg[q].x = pack2(v[0], v[1]);
            wreg[q].y = pack2(v[2], v[3]);
        }
    }

    // epilogue threads: tid<64, jj=tid, real if jj<50; handle BOTH batches
    const int jj  = tid;
    const bool epi = (tid < 64) && (jj < JPC);
    const int jg  = (int)rank * JPC + (epi ? jj : 0);
    float bir = 0.f, biz = 0.f, bin = 0.f, bhc = 0.f;
    if (epi) {
        bir = bi[0 * Hq + jg]; biz = bi[1 * Hq + jg];
        bin = bi[2 * Hq + jg]; bhc = bhn[jg];
    }
    const size_t hb0 = ((size_t)(b0g + 0) * Tq) * Hq + jg;
    const size_t hb1 = ((size_t)(b0g + 1) * Tq) * Hq + jg;
    const float* gxp = gsl + jj;     // + t*320 + b*160 (+0/+50/+100 per gate)

    // 2-deep gx pipeline (epi threads): [batch][gate]
    float g0r0 = 0.f, g0z0 = 0.f, g0n0 = 0.f, g0r1 = 0.f, g0z1 = 0.f, g0n1 = 0.f;
    float g1r0 = 0.f, g1z0 = 0.f, g1n0 = 0.f, g1r1 = 0.f, g1z1 = 0.f, g1n1 = 0.f;
    if (epi) {
        g0r0 = gxp[0];   g0z0 = gxp[50];       g0n0 = gxp[100];
        g0r1 = gxp[160]; g0z1 = gxp[210];      g0n1 = gxp[260];
        g1r0 = gxp[320]; g1z0 = gxp[370];      g1n0 = gxp[420];
        g1r1 = gxp[480]; g1z1 = gxp[530];      g1n1 = gxp[580];
    }
    float hp0 = 0.f, hp1 = 0.f;

    // all CTAs' SMEM (h zeros + mbars) ready before any arrive touches them
    asm volatile("barrier.cluster.arrive.aligned;" ::: "memory");
    asm volatile("barrier.cluster.wait.aligned;"   ::: "memory");
    if (tid == 0) {
        #pragma unroll
        for (uint32_t rr = 0; rr < CLUSTER; ++rr) {
            mbar_arrive_cluster(mb0, rr);
            mbar_arrive_cluster(mb1, rr);
        }
    }
    int ph0 = 0, ph1 = 0;
    if (wid == 9) { mbar_wait(mb0, ph0); }       // h0[0] ready (pre-arm)
    ph0 ^= 1;
    __syncthreads();

    for (int t = 0; t < Tq; ++t) {
        const int par = t & 1, nxt = par ^ 1;

        // ---------- phase 0: batch 0 ----------
        {
            const ulonglong2* vp =
                reinterpret_cast<const ulonglong2*>(&sm->h[par][0][kh * KHH]);
            unsigned long long a0 = 0, a1 = 0;
            #pragma unroll
            for (int q = 0; q < 26; ++q) {
                ulonglong2 v = vp[q];
                ffma2(a0, wreg[q].x, v.x);
                ffma2(a1, wreg[q].y, v.y);
            }
            sm->gh[kh][0][col] = fold2(a0, a1);
        }
        __syncthreads();
        if (epi) {
            float sr = sm->gh[0][0][jj]       + sm->gh[1][0][jj];
            float sz = sm->gh[0][0][50 + jj]  + sm->gh[1][0][50 + jj];
            float sn = sm->gh[0][0][100 + jj] + sm->gh[1][0][100 + jj];
            float r = sigf(g0r0 + sr + bir);
            float z = sigf(g0z0 + sz + biz);
            float n = tanh_fast(g0n0 + bin + r * (sn + bhc));
            float h = n + z * (hp0 - n);
            hp0 = h;
            uint32_t la = smem_u32(&sm->h[nxt][0][jg]);
            #pragma unroll
            for (uint32_t rr = 0; rr < CLUSTER; ++rr) st_cluster_f32(la, rr, h);
            g_h[hb0 + (size_t)t * Hq] = h;
        } else if (wid == 9) {
            mbar_wait(mb1, ph1);                 // h1[par] — hidden under epi0
        }
        ph1 ^= 1;
        __syncthreads();
        if (tid == 0) {
            #pragma unroll
            for (uint32_t rr = 0; rr < CLUSTER; ++rr) mbar_arrive_cluster(mb0, rr);
        }

        // ---------- phase 1: batch 1 ----------
        {
            const ulonglong2* vp =
                reinterpret_cast<const ulonglong2*>(&sm->h[par][1][kh * KHH]);
            unsigned long long a0 = 0, a1 = 0;
            #pragma unroll
            for (int q = 0; q < 26; ++q) {
                ulonglong2 v = vp[q];
                ffma2(a0, wreg[q].x, v.x);
                ffma2(a1, wreg[q].y, v.y);
            }
            sm->gh[kh][1][col] = fold2(a0, a1);
        }
        __syncthreads();
        if (epi) {
            float sr = sm->gh[0][1][jj]       + sm->gh[1][1][jj];
            float sz = sm->gh[0][1][50 + jj]  + sm->gh[1][1][50 + jj];
            float sn = sm->gh[0][1][100 + jj] + sm->gh[1][1][100 + jj];
            float r = sigf(g0r1 + sr + bir);
            float z = sigf(g0z1 + sz + biz);
            float n = tanh_fast(g0n1 + bin + r * (sn + bhc));
            float h = n + z * (hp1 - n);
            hp1 = h;
            uint32_t la = smem_u32(&sm->h[nxt][1][jg]);
            #pragma unroll
            for (uint32_t rr = 0; rr < CLUSTER; ++rr) st_cluster_f32(la, rr, h);
            g_h[hb1 + (size_t)t * Hq] = h;
        } else if (wid == 9 && t + 1 < Tq) {
            mbar_wait(mb0, ph0);                 // h0[nxt] — hidden under epi1
        }
        ph0 ^= 1;
        __syncthreads();
        if (tid == 0) {
            #pragma unroll
            for (uint32_t rr = 0; rr < CLUSTER; ++rr) mbar_arrive_cluster(mb1, rr);
        }

        // shift gx pipeline; prefetch t+2
        g0r0 = g1r0; g0z0 = g1z0; g0n0 = g1n0;
        g0r1 = g1r1; g0z1 = g1z1; g0n1 = g1n1;
        if (epi && (t + 2 < Tq)) {
            const float* p = gxp + (size_t)(t + 2) * (BG * 160);
            g1r0 = p[0];   g1z0 = p[50];  g1n0 = p[100];
            g1r1 = p[160]; g1z1 = p[210]; g1n1 = p[260];
        }
    }

    // no CTA may exit while peers' pushes/arrives into its SMEM are in flight
    asm volatile("barrier.cluster.arrive.aligned;" ::: "memory");
    asm volatile("barrier.cluster.wait.aligned;"   ::: "memory");
}

// ================= Phase C: y = h · Wo + bo =================
__global__ void __launch_bounds__(256)
y_kernel(const float* __restrict__ Wo, const float* __restrict__ bo,
         float* __restrict__ out)
{
    __shared__ float wos[Hq];
    const int tid = threadIdx.x;
    if (tid < Hq) wos[tid] = Wo[tid];
    __syncthreads();
    const float bo0 = bo[0];
    const int lane = tid & 31;
    const int gw   = (blockIdx.x * 256 + tid) >> 5;
    const int nw   = (gridDim.x * 256) >> 5;
    for (int row = gw; row < BT; row += nw) {
        const float* hr = g_h + (size_t)row * Hq;
        float s = 0.f;
        #pragma unroll
        for (int k = lane; k < Hq; k += 32) s = fmaf(hr[k], wos[k], s);
        #pragma unroll
        for (int m = 16; m > 0; m >>= 1) s += __shfl_xor_sync(0xffffffffu, s, m);
        if (lane == 0) out[row] = s + bo0;
    }
}

extern "C" void kernel_launch(void* const* d_in, const int* in_sizes, int n_in,
                              void* d_out, int out_size) {
    (void)in_sizes; (void)n_in; (void)out_size;
    const float* x   = (const float*)d_in[0];
    const float* Wi  = (const float*)d_in[1];
    const float* bi  = (const float*)d_in[2];
    const float* Wh  = (const float*)d_in[3];
    const float* bhn = (const float*)d_in[4];
    const float* Wo  = (const float*)d_in[5];
    const float* bo  = (const float*)d_in[6];
    float* out = (float*)d_out;

    cudaFuncSetAttribute(gru_kernel, cudaFuncAttributeMaxDynamicSharedMemorySize,
                         (int)sizeof(Smem));
    cudaLaunchConfig_t cfg = {};
    cfg.gridDim  = dim3(GRID, 1, 1);
    cfg.blockDim = dim3(NTHR, 1, 1);
    cfg.dynamicSmemBytes = sizeof(Smem);
    cfg.stream = 0;
    cudaLaunchAttribute attr[1];
    attr[0].id = cudaLaunchAttributeClusterDimension;
    attr[0].val.clusterDim.x = CLUSTER;
    attr[0].val.clusterDim.y = 1;
    attr[0].val.clusterDim.z = 1;
    cfg.attrs = attr;
    cfg.numAttrs = 1;
    cudaLaunchKernelEx(&cfg, gru_kernel, x, Wi, bi, Wh, bhn);

    y_kernel<<<592, 256>>>(Wo, bo, out);
}

// round 10
// speedup vs baseline: 1.8023x; 1.8023x over previous
#include <cuda_runtime.h>
#include <cstdint>

// GRU B=64,T=4096,F=100,H=200,O=1. 32 clusters x 4 CTAs, 320 thr.
// R7 base; single delta: per-step rendezvous is an SMEM mbarrier (count=4).
// Threads 0-3 fire one remote arrive.release each (no thread stall); only
// warp 9 polls try_wait (HW-sleep), a __syncthreads releases the rest.
// Phase A: CTA-private gx = x·Wi -> scratch. Phase C: y GEMV (47us measured).

#define Bq      64
#define Tq      4096
#define Fq      100
#define Hq      200
#define G3      600
#define BT      (Bq * Tq)
#define CLUSTER 4
#define BG      2
#define JPC     50
#define NTHR    320
#define KHH     104              // K-half of padded 208
#define TT      32               // phase-A tile rows
#define GRID    128

__device__ float g_gx[(size_t)GRID * Tq * BG * 160];   // CTA-private [t][b][160]
__device__ float g_h [(size_t)BT * Hq];                // [row=b*Tq+t][200]

__device__ __forceinline__ uint32_t smem_u32(const void* p) {
    return (uint32_t)__cvta_generic_to_shared(p);
}
__device__ __forceinline__ void st_cluster_f32(uint32_t laddr, uint32_t rr, float v) {
    uint32_t ra;
    asm volatile("mapa.shared::cluster.u32 %0, %1, %2;" : "=r"(ra) : "r"(laddr), "r"(rr));
    asm volatile("st.shared::cluster.f32 [%0], %1;" :: "r"(ra), "f"(v) : "memory");
}
__device__ __forceinline__ void mbar_init(uint32_t a, uint32_t cnt) {
    asm volatile("mbarrier.init.shared.b64 [%0], %1;" :: "r"(a), "r"(cnt) : "memory");
}
__device__ __forceinline__ void mbar_arrive_cluster(uint32_t local_a, uint32_t rr) {
    asm volatile(
        "{\n\t.reg .b32 ra;\n\t"
        "mapa.shared::cluster.u32 ra, %0, %1;\n\t"
        "mbarrier.arrive.release.cluster.shared::cluster.b64 _, [ra];\n\t}"
        :: "r"(local_a), "r"(rr) : "memory");
}
__device__ __forceinline__ void mbar_wait(uint32_t a, uint32_t parity) {
    asm volatile(
        "{\n\t.reg .pred P;\n\t"
        "WL_%=:\n\t"
        "mbarrier.try_wait.parity.acquire.cluster.shared::cta.b64 P, [%0], %1, 0x989680;\n\t"
        "@P bra.uni WD_%=;\n\t"
        "bra.uni WL_%=;\n\t"
        "WD_%=:\n\t}"
        :: "r"(a), "r"(parity) : "memory");
}
__device__ __forceinline__ void ffma2(unsigned long long& acc,
                                      unsigned long long a, unsigned long long b) {
    asm("fma.rn.f32x2 %0, %1, %2, %0;" : "+l"(acc) : "l"(a), "l"(b));
}
__device__ __forceinline__ float fold2(unsigned long long a, unsigned long long b) {
    unsigned long long s;
    asm("add.rn.f32x2 %0, %1, %2;" : "=l"(s) : "l"(a), "l"(b));
    return __uint_as_float((unsigned)s) + __uint_as_float((unsigned)(s >> 32));
}
__device__ __forceinline__ unsigned long long pack2(float a, float b) {
    return (unsigned long long)__float_as_uint(a) |
           ((unsigned long long)__float_as_uint(b) << 32);
}
__device__ __forceinline__ float sigf(float x) {
    return __fdividef(1.0f, 1.0f + __expf(-x));
}
__device__ __forceinline__ float tanh_fast(float x) {
    return 2.0f * sigf(2.0f * x) - 1.0f;
}

struct __align__(16) Smem {
    float h[2][BG][208];        // parity, batch (pads 200..207 zeroed)
    float gh[2][BG][160];       // K-half partials [kh][b][col]
    float bi_s[160];
    float bhn_s[64];
    float xs[BG][TT][104];      // phase-A staging (pads 100..103 zeroed)
    unsigned long long mbar;
};

__global__ void __launch_bounds__(NTHR, 1)
gru_kernel(const float* __restrict__ x,  const float* __restrict__ Wi,
           const float* __restrict__ bi, const float* __restrict__ Wh,
           const float* __restrict__ bhn)
{
    extern __shared__ char smraw[];
    Smem* sm = reinterpret_cast<Smem*>(smraw);
    const int tid = threadIdx.x;
    uint32_t rank;
    asm("mov.u32 %0, %%cluster_ctarank;" : "=r"(rank));
    const int b0g = (blockIdx.x >> 2) * BG;
    float* gsl = &g_gx[(size_t)blockIdx.x * Tq * (BG * 160)];
    const uint32_t mba = smem_u32(&sm->mbar);

    // ---- one-time SMEM init ----
    for (int i = tid; i < 2 * BG * 208; i += NTHR)
        (&sm->h[0][0][0])[i] = 0.f;
    for (int i = tid; i < 160; i += NTHR) {
        float v = 0.f;
        if (i < 150) { int g = i / JPC, jj = i - g * JPC; v = bi[g * Hq + (int)rank * JPC + jj]; }
        sm->bi_s[i] = v;
    }
    if (tid < JPC) sm->bhn_s[tid] = bhn[(int)rank * JPC + tid];
    for (int i = tid; i < BG * TT * 4; i += NTHR) {
        int b2 = i / (TT * 4), rem = i - b2 * (TT * 4);
        sm->xs[b2][rem >> 2][100 + (rem & 3)] = 0.f;
    }
    if (tid == 0) mbar_init(mba, CLUSTER);
    __syncthreads();

    // ================= Phase A: gx = x · Wi (CTA-private slice) =================
    {
        const int c   = tid >> 1;        // 0..159 (c<150 real)
        const int b   = tid & 1;
        const bool act = (c < 150);
        int gcol = 0;
        if (act) { int g = c / JPC, j2 = c - g * JPC; gcol = g * Hq + (int)rank * JPC + j2; }

        ulonglong2 wr[26];               // k = 0..103 (100 real + 4 zero pad)
        #pragma unroll
        for (int q = 0; q < 26; ++q) {
            float v[4];
            #pragma unroll
            for (int r = 0; r < 4; ++r) {
                int k = q * 4 + r;
                v[r] = (act && k < Fq) ? Wi[(size_t)k * G3 + gcol] : 0.f;
            }
            wr[q].x = pack2(v[0], v[1]);
            wr[q].y = pack2(v[2], v[3]);
        }

        for (int t0 = 0; t0 < Tq; t0 += TT) {
            __syncthreads();
            for (int i = tid; i < BG * TT * Fq; i += NTHR) {
                int b2 = i / (TT * Fq), rem = i - b2 * (TT * Fq);
                int r = rem / Fq, f = rem - r * Fq;
                sm->xs[b2][r][f] =
                    x[(size_t)(b0g + b2) * (Tq * Fq) + (size_t)(t0 + r) * Fq + f];
            }
            __syncthreads();
            if (act) {
                for (int r = 0; r < TT; ++r) {
                    const ulonglong2* vp = reinterpret_cast<const ulonglong2*>(sm->xs[b][r]);
                    unsigned long long a0 = 0, a1 = 0;
                    #pragma unroll
                    for (int q = 0; q < 26; ++q) {
                        ulonglong2 v = vp[q];
                        ffma2(a0, wr[q].x, v.x);
                        ffma2(a1, wr[q].y, v.y);
                    }
                    gsl[(size_t)(t0 + r) * (BG * 160) + b * 160 + c] = fold2(a0, a1);
                }
            }
        }
    }
    __syncthreads();   // gsl visible CTA-wide

    // ================= Phase B: recurrence =================
    const int wid  = tid >> 5, lane = tid & 31;
    const int kh   = (wid >= 5);                         // K-half
    const int col  = (kh ? wid - 5 : wid) * 32 + lane;   // 0..159 (150 real)

    // register-resident Wh: column col, K-half slice (104 floats = 52 regs)
    ulonglong2 wreg[26];
    {
        int gcol = 0;
        const bool real = (col < 150);
        if (real) {
            int g = col / JPC, jj = col - g * JPC;
            gcol = g * Hq + (int)rank * JPC + jj;
        }
        #pragma unroll
        for (int q = 0; q < 26; ++q) {
            float v[4];
            #pragma unroll
            for (int r = 0; r < 4; ++r) {
                int k = kh * KHH + q * 4 + r;
                v[r] = (real && k < Hq) ? Wh[(size_t)k * G3 + gcol] : 0.f;
            }
            wreg[q].x = pack2(v[0], v[1]);
            wreg[q].y = pack2(v[2], v[3]);
        }
    }

    const int eb = tid >> 6, jj = tid & 63;      // epilogue map (tid<128, jj<50)
    const bool epi = (tid < 128) && (jj < JPC);
    const int jg = (int)rank * JPC + jj;
    const size_t gxo   = epi ? ((size_t)eb * 160 + jj) : 0;
    const size_t hbase = epi ? ((size_t)(b0g + eb) * Tq) * Hq + jg : 0;

    // 2-deep gx register pipeline: g0 = gx(t), g1 = gx(t+1)
    float g0r = 0.f, g0z = 0.f, g0n = 0.f;
    float g1r = 0.f, g1z = 0.f, g1n = 0.f;
    if (epi) {
        g0r = gsl[gxo];       g0z = gsl[gxo + 50];       g0n = gsl[gxo + 100];
        const float* p = gsl + (BG * 160) + gxo;
        g1r = p[0];           g1z = p[50];               g1n = p[100];
    }

    // all CTAs' SMEM (h zeros + mbar) initialized before any arrive/push
    asm volatile("barrier.cluster.arrive.aligned;" ::: "memory");
    asm volatile("barrier.cluster.wait.aligned;"   ::: "memory");
    if (tid < CLUSTER) mbar_arrive_cluster(mba, (uint32_t)tid);   // step "-1": h[0] ready

    int ph = 0;
    for (int t = 0; t < Tq; ++t) {
        const int par = t & 1, nxt = par ^ 1;

        // rendezvous: only warp 9 polls; everyone else parked at the barrier
        if (wid == 9) mbar_wait(mba, ph);
        ph ^= 1;
        __syncthreads();                         // h[par] ready for all warps

        // ---- dot: K-half, both batches, warp-uniform broadcast loads ----
        {
            const ulonglong2* vp0 = reinterpret_cast<const ulonglong2*>(&sm->h[par][0][kh * KHH]);
            const ulonglong2* vp1 = reinterpret_cast<const ulonglong2*>(&sm->h[par][1][kh * KHH]);
            unsigned long long a0x = 0, a0y = 0, a1x = 0, a1y = 0;
            #pragma unroll
            for (int q = 0; q < 26; ++q) {
                ulonglong2 v0 = vp0[q], v1 = vp1[q];
                ffma2(a0x, wreg[q].x, v0.x); ffma2(a0y, wreg[q].y, v0.y);
                ffma2(a1x, wreg[q].x, v1.x); ffma2(a1y, wreg[q].y, v1.y);
            }
            sm->gh[kh][0][col] = fold2(a0x, a0y);
            sm->gh[kh][1][col] = fold2(a1x, a1y);
        }
        __syncthreads();

        // ---- epilogue: gates, h update, DSMEM exchange, h -> scratch ----
        if (epi) {
            int cr = jj, cz = JPC + jj, cn = 2 * JPC + jj;
            float ar  = g0r + sm->gh[0][eb][cr] + sm->gh[1][eb][cr] + sm->bi_s[cr];
            float az  = g0z + sm->gh[0][eb][cz] + sm->gh[1][eb][cz] + sm->bi_s[cz];
            float ghn = sm->gh[0][eb][cn] + sm->gh[1][eb][cn] + sm->bhn_s[jj];
            float r = sigf(ar), z = sigf(az);
            float n = tanh_fast(g0n + sm->bi_s[cn] + r * ghn);
            float hold = sm->h[par][eb][jg];
            float hnew = n + z * (hold - n);
            uint32_t la = smem_u32(&sm->h[nxt][eb][jg]);
            #pragma unroll
            for (uint32_t rr = 0; rr < CLUSTER; ++rr) st_cluster_f32(la, rr, hnew);
            g_h[hbase + (size_t)t * Hq] = hnew;
        }
        __syncthreads();                         // all pushes issued

        // fire-and-forget arrives (release orders the fabric, no thread stall)
        if (tid < CLUSTER) mbar_arrive_cluster(mba, (uint32_t)tid);

        // shift gx pipeline; prefetch t+2
        g0r = g1r; g0z = g1z; g0n = g1n;
        if (epi && (t + 2 < Tq)) {
            const float* p = gsl + (size_t)(t + 2) * (BG * 160) + gxo;
            g1r = p[0]; g1z = p[50]; g1n = p[100];
        }
    }

    // no CTA may exit while peers' pushes/arrives into its SMEM are in flight
    asm volatile("barrier.cluster.arrive.aligned;" ::: "memory");
    asm volatile("barrier.cluster.wait.aligned;"   ::: "memory");
}

// ================= Phase C: y = h · Wo + bo =================
__global__ void __launch_bounds__(256)
y_kernel(const float* __restrict__ Wo, const float* __restrict__ bo,
         float* __restrict__ out)
{
    __shared__ float wos[Hq];
    const int tid = threadIdx.x;
    if (tid < Hq) wos[tid] = Wo[tid];
    __syncthreads();
    const float bo0 = bo[0];
    const int lane = tid & 31;
    const int gw   = (blockIdx.x * 256 + tid) >> 5;
    const int nw   = (gridDim.x * 256) >> 5;
    for (int row = gw; row < BT; row += nw) {
        const float* hr = g_h + (size_t)row * Hq;
        float s = 0.f;
        #pragma unroll
        for (int k = lane; k < Hq; k += 32) s = fmaf(hr[k], wos[k], s);
        #pragma unroll
        for (int m = 16; m > 0; m >>= 1) s += __shfl_xor_sync(0xffffffffu, s, m);
        if (lane == 0) out[row] = s + bo0;
    }
}

extern "C" void kernel_launch(void* const* d_in, const int* in_sizes, int n_in,
                              void* d_out, int out_size) {
    (void)in_sizes; (void)n_in; (void)out_size;
    const float* x   = (const float*)d_in[0];
    const float* Wi  = (const float*)d_in[1];
    const float* bi  = (const float*)d_in[2];
    const float* Wh  = (const float*)d_in[3];
    const float* bhn = (const float*)d_in[4];
    const float* Wo  = (const float*)d_in[5];
    const float* bo  = (const float*)d_in[6];
    float* out = (float*)d_out;

    cudaFuncSetAttribute(gru_kernel, cudaFuncAttributeMaxDynamicSharedMemorySize,
                         (int)sizeof(Smem));
    cudaLaunchConfig_t cfg = {};
    cfg.gridDim  = dim3(GRID, 1, 1);
    cfg.blockDim = dim3(NTHR, 1, 1);
    cfg.dynamicSmemBytes = sizeof(Smem);
    cfg.stream = 0;
    cudaLaunchAttribute attr[1];
    attr[0].id = cudaLaunchAttributeClusterDimension;
    attr[0].val.clusterDim.x = CLUSTER;
    attr[0].val.clusterDim.y = 1;
    attr[0].val.clusterDim.z = 1;
    cfg.attrs = attr;
    cfg.numAttrs = 1;
    cudaLaunchKernelEx(&cfg, gru_kernel, x, Wi, bi, Wh, bhn);

    y_kernel<<<592, 256>>>(Wo, bo, out);
}

// round 11
// speedup vs baseline: 1.9980x; 1.1086x over previous
#include <cuda_runtime.h>
#include <cstdint>

// GRU B=64,T=4096,F=100,H=200,O=1. 32 clusters x 4 CTAs, 320 thr. R7 compute.
// Delta: NO per-step cluster rendezvous. h stored as 4 chunks of 52 (50 real+2 pad),
// chunk r written only by CTA r. Producers post per-CTA step-counter flags
// (st.release.cluster) after pushes; each dot warp acquire-polls only the flag of
// the chunk it is about to consume. Rendezvous latency hides under the epilogue.

#define Bq      64
#define Tq      4096
#define Fq      100
#define Hq      200
#define G3      600
#define BT      (Bq * Tq)
#define CLUSTER 4
#define BG      2
#define JPC     50
#define NTHR    320
#define KHH     104              // K-half = 2 chunks of 52
#define TT      32               // phase-A tile rows
#define GRID    128

__device__ float g_gx[(size_t)GRID * Tq * BG * 160];   // CTA-private [t][b][160]
__device__ float g_h [(size_t)BT * Hq];                // [row=b*Tq+t][200]

__device__ __forceinline__ uint32_t smem_u32(const void* p) {
    return (uint32_t)__cvta_generic_to_shared(p);
}
__device__ __forceinline__ void st_cluster_f32(uint32_t laddr, uint32_t rr, float v) {
    uint32_t ra;
    asm volatile("mapa.shared::cluster.u32 %0, %1, %2;" : "=r"(ra) : "r"(laddr), "r"(rr));
    asm volatile("st.shared::cluster.f32 [%0], %1;" :: "r"(ra), "f"(v) : "memory");
}
__device__ __forceinline__ void st_cluster_rel_u32(uint32_t laddr, uint32_t rr, uint32_t v) {
    uint32_t ra;
    asm volatile("mapa.shared::cluster.u32 %0, %1, %2;" : "=r"(ra) : "r"(laddr), "r"(rr));
    asm volatile("st.release.cluster.shared::cluster.u32 [%0], %1;" :: "r"(ra), "r"(v) : "memory");
}
__device__ __forceinline__ void flag_wait_ge(uint32_t a, uint32_t target) {
    asm volatile(
        "{\n\t.reg .pred P;\n\t.reg .u32 v;\n\t"
        "FW_%=:\n\t"
        "ld.acquire.cluster.shared::cta.u32 v, [%0];\n\t"
        "setp.lt.u32 P, v, %1;\n\t"
        "@P bra FW_%=;\n\t}"
        :: "r"(a), "r"(target) : "memory");
}
__device__ __forceinline__ void ffma2(unsigned long long& acc,
                                      unsigned long long a, unsigned long long b) {
    asm("fma.rn.f32x2 %0, %1, %2, %0;" : "+l"(acc) : "l"(a), "l"(b));
}
__device__ __forceinline__ float fold2(unsigned long long a, unsigned long long b) {
    unsigned long long s;
    asm("add.rn.f32x2 %0, %1, %2;" : "=l"(s) : "l"(a), "l"(b));
    return __uint_as_float((unsigned)s) + __uint_as_float((unsigned)(s >> 32));
}
__device__ __forceinline__ unsigned long long pack2(float a, float b) {
    return (unsigned long long)__float_as_uint(a) |
           ((unsigned long long)__float_as_uint(b) << 32);
}
__device__ __forceinline__ float sigf(float x) {
    return __fdividef(1.0f, 1.0f + __expf(-x));
}
__device__ __forceinline__ float tanh_fast(float x) {
    return 2.0f * sigf(2.0f * x) - 1.0f;
}

struct __align__(16) Smem {
    float h[2][BG][208];        // 4 chunks of 52 per batch (pads zeroed, never rewritten)
    float gh[2][BG][160];       // K-half partials [kh][b][col]
    float bi_s[160];
    float bhn_s[64];
    float xs[BG][TT][104];      // phase-A staging (pads zeroed)
    uint32_t flag[4];           // flag[src] = steps completed by CTA src
};

__global__ void __launch_bounds__(NTHR, 1)
gru_kernel(const float* __restrict__ x,  const float* __restrict__ Wi,
           const float* __restrict__ bi, const float* __restrict__ Wh,
           const float* __restrict__ bhn)
{
    extern __shared__ char smraw[];
    Smem* sm = reinterpret_cast<Smem*>(smraw);
    const int tid = threadIdx.x;
    uint32_t rank;
    asm("mov.u32 %0, %%cluster_ctarank;" : "=r"(rank));
    const int b0g = (blockIdx.x >> 2) * BG;
    float* gsl = &g_gx[(size_t)blockIdx.x * Tq * (BG * 160)];

    // ---- one-time SMEM init ----
    for (int i = tid; i < 2 * BG * 208; i += NTHR)
        (&sm->h[0][0][0])[i] = 0.f;
    for (int i = tid; i < 160; i += NTHR) {
        float v = 0.f;
        if (i < 150) { int g = i / JPC, jj = i - g * JPC; v = bi[g * Hq + (int)rank * JPC + jj]; }
        sm->bi_s[i] = v;
    }
    if (tid < JPC) sm->bhn_s[tid] = bhn[(int)rank * JPC + tid];
    for (int i = tid; i < BG * TT * 4; i += NTHR) {
        int b2 = i / (TT * 4), rem = i - b2 * (TT * 4);
        sm->xs[b2][rem >> 2][100 + (rem & 3)] = 0.f;
    }
    if (tid < 4) sm->flag[tid] = 0u;
    __syncthreads();

    // ================= Phase A: gx = x · Wi (CTA-private slice) =================
    {
        const int c   = tid >> 1;        // 0..159 (c<150 real)
        const int b   = tid & 1;
        const bool act = (c < 150);
        int gcol = 0;
        if (act) { int g = c / JPC, j2 = c - g * JPC; gcol = g * Hq + (int)rank * JPC + j2; }

        ulonglong2 wr[26];               // k = 0..103 (100 real + 4 zero pad)
        #pragma unroll
        for (int q = 0; q < 26; ++q) {
            float v[4];
            #pragma unroll
            for (int r = 0; r < 4; ++r) {
                int k = q * 4 + r;
                v[r] = (act && k < Fq) ? Wi[(size_t)k * G3 + gcol] : 0.f;
            }
            wr[q].x = pack2(v[0], v[1]);
            wr[q].y = pack2(v[2], v[3]);
        }

        for (int t0 = 0; t0 < Tq; t0 += TT) {
            __syncthreads();
            for (int i = tid; i < BG * TT * Fq; i += NTHR) {
                int b2 = i / (TT * Fq), rem = i - b2 * (TT * Fq);
                int r = rem / Fq, f = rem - r * Fq;
                sm->xs[b2][r][f] =
                    x[(size_t)(b0g + b2) * (Tq * Fq) + (size_t)(t0 + r) * Fq + f];
            }
            __syncthreads();
            if (act) {
                for (int r = 0; r < TT; ++r) {
                    const ulonglong2* vp = reinterpret_cast<const ulonglong2*>(sm->xs[b][r]);
                    unsigned long long a0 = 0, a1 = 0;
                    #pragma unroll
                    for (int q = 0; q < 26; ++q) {
                        ulonglong2 v = vp[q];
                        ffma2(a0, wr[q].x, v.x);
                        ffma2(a1, wr[q].y, v.y);
                    }
                    gsl[(size_t)(t0 + r) * (BG * 160) + b * 160 + c] = fold2(a0, a1);
                }
            }
        }
    }
    __syncthreads();   // gsl visible CTA-wide

    // ================= Phase B: recurrence (dataflow flags) =================
    const int wid  = tid >> 5, lane = tid & 31;
    const int kh   = (wid >= 5);                         // K-half = chunks {2kh, 2kh+1}
    const int col  = (kh ? wid - 5 : wid) * 32 + lane;   // 0..159 (150 real)

    // register-resident Wh, chunked layout: pos p = kh*104 + 4q + r -> chunk c=p/52,
    // within w=p%52; real h index = 50c + w (w<50), pads zero.
    ulonglong2 wreg[26];
    {
        int gcol = 0;
        const bool real = (col < 150);
        if (real) {
            int g = col / JPC, jj = col - g * JPC;
            gcol = g * Hq + (int)rank * JPC + jj;
        }
        #pragma unroll
        for (int q = 0; q < 26; ++q) {
            float v[4];
            #pragma unroll
            for (int r = 0; r < 4; ++r) {
                int p = kh * KHH + q * 4 + r;
                int c2 = p / 52, w = p - c2 * 52;
                v[r] = (real && w < 50) ? Wh[(size_t)(c2 * 50 + w) * G3 + gcol] : 0.f;
            }
            wreg[q].x = pack2(v[0], v[1]);
            wreg[q].y = pack2(v[2], v[3]);
        }
    }

    const int eb = tid >> 6, jj = tid & 63;      // epilogue map (tid<128, jj<50)
    const bool epi = (tid < 128) && (jj < JPC);
    const int jg  = (int)rank * JPC + jj;            // global h index (for g_h)
    const int jsm = (int)rank * 52 + jj;             // chunked SMEM position
    const size_t gxo   = epi ? ((size_t)eb * 160 + jj) : 0;
    const size_t hbase = epi ? ((size_t)(b0g + eb) * Tq) * Hq + jg : 0;

    const uint32_t fa0 = smem_u32(&sm->flag[2 * kh]);
    const uint32_t fa1 = smem_u32(&sm->flag[2 * kh + 1]);
    const uint32_t fmy = smem_u32(&sm->flag[rank]);

    // 2-deep gx register pipeline
    float g0r = 0.f, g0z = 0.f, g0n = 0.f;
    float g1r = 0.f, g1z = 0.f, g1n = 0.f;
    if (epi) {
        g0r = gsl[gxo];       g0z = gsl[gxo + 50];       g0n = gsl[gxo + 100];
        const float* p = gsl + (BG * 160) + gxo;
        g1r = p[0];           g1z = p[50];               g1n = p[100];
    }

    // all CTAs' SMEM (h zeros + flags) initialized before any push/flag lands
    asm volatile("barrier.cluster.arrive.aligned;" ::: "memory");
    asm volatile("barrier.cluster.wait.aligned;"   ::: "memory");

    for (int t = 0; t < Tq; ++t) {
        const int par = t & 1, nxt = par ^ 1;
        const uint32_t need = (uint32_t)t;

        // ---- dot: chunk-guarded. Poll only the flag of the chunk consumed next. ----
        {
            const ulonglong2* vp0 = reinterpret_cast<const ulonglong2*>(&sm->h[par][0][kh * KHH]);
            const ulonglong2* vp1 = reinterpret_cast<const ulonglong2*>(&sm->h[par][1][kh * KHH]);
            unsigned long long a0x = 0, a0y = 0, a1x = 0, a1y = 0;

            flag_wait_ge(fa0, need);                 // chunk 2kh ready
            #pragma unroll
            for (int q = 0; q < 13; ++q) {
                ulonglong2 v0 = vp0[q], v1 = vp1[q];
                ffma2(a0x, wreg[q].x, v0.x); ffma2(a0y, wreg[q].y, v0.y);
                ffma2(a1x, wreg[q].x, v1.x); ffma2(a1y, wreg[q].y, v1.y);
            }
            flag_wait_ge(fa1, need);                 // chunk 2kh+1 ready
            #pragma unroll
            for (int q = 13; q < 26; ++q) {
                ulonglong2 v0 = vp0[q], v1 = vp1[q];
                ffma2(a0x, wreg[q].x, v0.x); ffma2(a0y, wreg[q].y, v0.y);
                ffma2(a1x, wreg[q].x, v1.x); ffma2(a1y, wreg[q].y, v1.y);
            }
            sm->gh[kh][0][col] = fold2(a0x, a0y);
            sm->gh[kh][1][col] = fold2(a1x, a1y);
        }
        __syncthreads();

        // ---- epilogue: gates, h update, DSMEM pushes, h -> scratch ----
        if (epi) {
            int cr = jj, cz = JPC + jj, cn = 2 * JPC + jj;
            float ar  = g0r + sm->gh[0][eb][cr] + sm->gh[1][eb][cr] + sm->bi_s[cr];
            float az  = g0z + sm->gh[0][eb][cz] + sm->gh[1][eb][cz] + sm->bi_s[cz];
            float ghn = sm->gh[0][eb][cn] + sm->gh[1][eb][cn] + sm->bhn_s[jj];
            float r = sigf(ar), z = sigf(az);
            float n = tanh_fast(g0n + sm->bi_s[cn] + r * ghn);
            float hold = sm->h[par][eb][jsm];        // own chunk, own thread's push
            float hnew = n + z * (hold - n);
            uint32_t la = smem_u32(&sm->h[nxt][eb][jsm]);
            #pragma unroll
            for (uint32_t rr = 0; rr < CLUSTER; ++rr) st_cluster_f32(la, rr, hnew);
            g_h[hbase + (size_t)t * Hq] = hnew;
        }
        __syncthreads();                              // all pushes issued

        // post my flag = t+1 to all CTAs (release orders the pushes; no stall)
        if (tid < CLUSTER) st_cluster_rel_u32(fmy, (uint32_t)tid, (uint32_t)(t + 1));

        // shift gx pipeline; prefetch t+2
        g0r = g1r; g0z = g1z; g0n = g1n;
        if (epi && (t + 2 < Tq)) {
            const float* p = gsl + (size_t)(t + 2) * (BG * 160) + gxo;
            g1r = p[0]; g1z = p[50]; g1n = p[100];
        }
    }

    // no CTA exits while peers' pushes/flags into its SMEM are in flight
    asm volatile("barrier.cluster.arrive.aligned;" ::: "memory");
    asm volatile("barrier.cluster.wait.aligned;"   ::: "memory");
}

// ================= Phase C: y = h · Wo + bo =================
__global__ void __launch_bounds__(256)
y_kernel(const float* __restrict__ Wo, const float* __restrict__ bo,
         float* __restrict__ out)
{
    __shared__ float wos[Hq];
    const int tid = threadIdx.x;
    if (tid < Hq) wos[tid] = Wo[tid];
    __syncthreads();
    const float bo0 = bo[0];
    const int lane = tid & 31;
    const int gw   = (blockIdx.x * 256 + tid) >> 5;
    const int nw   = (gridDim.x * 256) >> 5;
    for (int row = gw; row < BT; row += nw) {
        const float* hr = g_h + (size_t)row * Hq;
        float s = 0.f;
        #pragma unroll
        for (int k = lane; k < Hq; k += 32) s = fmaf(hr[k], wos[k], s);
        #pragma unroll
        for (int m = 16; m > 0; m >>= 1) s += __shfl_xor_sync(0xffffffffu, s, m);
        if (lane == 0) out[row] = s + bo0;
    }
}

extern "C" void kernel_launch(void* const* d_in, const int* in_sizes, int n_in,
                              void* d_out, int out_size) {
    (void)in_sizes; (void)n_in; (void)out_size;
    const float* x   = (const float*)d_in[0];
    const float* Wi  = (const float*)d_in[1];
    const float* bi  = (const float*)d_in[2];
    const float* Wh  = (const float*)d_in[3];
    const float* bhn = (const float*)d_in[4];
    const float* Wo  = (const float*)d_in[5];
    const float* bo  = (const float*)d_in[6];
    float* out = (float*)d_out;

    cudaFuncSetAttribute(gru_kernel, cudaFuncAttributeMaxDynamicSharedMemorySize,
                         (int)sizeof(Smem));
    cudaLaunchConfig_t cfg = {};
    cfg.gridDim  = dim3(GRID, 1, 1);
    cfg.blockDim = dim3(NTHR, 1, 1);
    cfg.dynamicSmemBytes = sizeof(Smem);
    cfg.stream = 0;
    cudaLaunchAttribute attr[1];
    attr[0].id = cudaLaunchAttributeClusterDimension;
    attr[0].val.clusterDim.x = CLUSTER;
    attr[0].val.clusterDim.y = 1;
    attr[0].val.clusterDim.z = 1;
    cfg.attrs = attr;
    cfg.numAttrs = 1;
    cudaLaunchKernelEx(&cfg, gru_kernel, x, Wi, bi, Wh, bhn);

    y_kernel<<<592, 256>>>(Wo, bo, out);
}

// round 12
// speedup vs baseline: 2.2750x; 1.1386x over previous
#include <cuda_runtime.h>
#include <cstdint>

// GRU B=64,T=4096,F=100,H=200,O=1. R7 base (best: 8120us), 32 clusters x 4 CTAs, 320 thr.
// Deltas: (1) tanh.approx gates; (2) own-rank h push = plain STS; (3) g_h STG moved
// after cluster.arrive; (4) 5 no-op launches so ncu -s5 -c1 captures gru_kernel.

#define Bq      64
#define Tq      4096
#define Fq      100
#define Hq      200
#define G3      600
#define BT      (Bq * Tq)
#define CLUSTER 4
#define BG      2
#define JPC     50
#define NTHR    320
#define KHH     104              // K-half of padded 208
#define TT      32               // phase-A tile rows
#define GRID    128

__device__ float g_gx[(size_t)GRID * Tq * BG * 160];   // CTA-private [t][b][160]
__device__ float g_h [(size_t)BT * Hq];                // [row=b*Tq+t][200]
__device__ int   g_dummy;

__device__ __forceinline__ uint32_t smem_u32(const void* p) {
    return (uint32_t)__cvta_generic_to_shared(p);
}
__device__ __forceinline__ void st_cluster_f32(uint32_t laddr, uint32_t rr, float v) {
    uint32_t ra;
    asm volatile("mapa.shared::cluster.u32 %0, %1, %2;" : "=r"(ra) : "r"(laddr), "r"(rr));
    asm volatile("st.shared::cluster.f32 [%0], %1;" :: "r"(ra), "f"(v) : "memory");
}
__device__ __forceinline__ void ffma2(unsigned long long& acc,
                                      unsigned long long a, unsigned long long b) {
    asm("fma.rn.f32x2 %0, %1, %2, %0;" : "+l"(acc) : "l"(a), "l"(b));
}
__device__ __forceinline__ float fold2(unsigned long long a, unsigned long long b) {
    unsigned long long s;
    asm("add.rn.f32x2 %0, %1, %2;" : "=l"(s) : "l"(a), "l"(b));
    return __uint_as_float((unsigned)s) + __uint_as_float((unsigned)(s >> 32));
}
__device__ __forceinline__ unsigned long long pack2(float a, float b) {
    return (unsigned long long)__float_as_uint(a) |
           ((unsigned long long)__float_as_uint(b) << 32);
}
__device__ __forceinline__ float tanh_fast(float x) {
    float t;
    asm("tanh.approx.f32 %0, %1;" : "=f"(t) : "f"(x));
    return t;
}
__device__ __forceinline__ float sigf(float x) {
    return 0.5f * tanh_fast(0.5f * x) + 0.5f;
}

struct __align__(16) Smem {
    float h[2][BG][208];        // parity, batch (pads 200..207 zeroed)
    float gh[2][BG][160];       // K-half partials [kh][b][col]
    float bi_s[160];
    float bhn_s[64];
    float xs[BG][TT][104];      // phase-A staging (pads 100..103 zeroed)
};

__global__ void nop_kernel() {
    if (threadIdx.x == 1024) g_dummy = 1;   // never true; keeps launch non-empty
}

__global__ void __launch_bounds__(NTHR, 1)
gru_kernel(const float* __restrict__ x,  const float* __restrict__ Wi,
           const float* __restrict__ bi, const float* __restrict__ Wh,
           const float* __restrict__ bhn)
{
    extern __shared__ char smraw[];
    Smem* sm = reinterpret_cast<Smem*>(smraw);
    const int tid = threadIdx.x;
    uint32_t rank;
    asm("mov.u32 %0, %%cluster_ctarank;" : "=r"(rank));
    const int b0g = (blockIdx.x >> 2) * BG;
    float* gsl = &g_gx[(size_t)blockIdx.x * Tq * (BG * 160)];

    // ---- one-time SMEM init ----
    for (int i = tid; i < 2 * BG * 208; i += NTHR)
        (&sm->h[0][0][0])[i] = 0.f;
    for (int i = tid; i < 160; i += NTHR) {
        float v = 0.f;
        if (i < 150) { int g = i / JPC, jj = i - g * JPC; v = bi[g * Hq + (int)rank * JPC + jj]; }
        sm->bi_s[i] = v;
    }
    if (tid < JPC) sm->bhn_s[tid] = bhn[(int)rank * JPC + tid];
    for (int i = tid; i < BG * TT * 4; i += NTHR) {
        int b2 = i / (TT * 4), rem = i - b2 * (TT * 4);
        sm->xs[b2][rem >> 2][100 + (rem & 3)] = 0.f;
    }

    // ================= Phase A: gx = x · Wi (CTA-private slice) =================
    {
        const int c   = tid >> 1;        // 0..159 (c<150 real)
        const int b   = tid & 1;
        const bool act = (c < 150);
        int gcol = 0;
        if (act) { int g = c / JPC, j2 = c - g * JPC; gcol = g * Hq + (int)rank * JPC + j2; }

        ulonglong2 wr[26];               // k = 0..103 (100 real + 4 zero pad)
        #pragma unroll
        for (int q = 0; q < 26; ++q) {
            float v[4];
            #pragma unroll
            for (int r = 0; r < 4; ++r) {
                int k = q * 4 + r;
                v[r] = (act && k < Fq) ? Wi[(size_t)k * G3 + gcol] : 0.f;
            }
            wr[q].x = pack2(v[0], v[1]);
            wr[q].y = pack2(v[2], v[3]);
        }

        for (int t0 = 0; t0 < Tq; t0 += TT) {
            __syncthreads();
            for (int i = tid; i < BG * TT * Fq; i += NTHR) {
                int b2 = i / (TT * Fq), rem = i - b2 * (TT * Fq);
                int r = rem / Fq, f = rem - r * Fq;
                sm->xs[b2][r][f] =
                    x[(size_t)(b0g + b2) * (Tq * Fq) + (size_t)(t0 + r) * Fq + f];
            }
            __syncthreads();
            if (act) {
                for (int r = 0; r < TT; ++r) {
                    const ulonglong2* vp = reinterpret_cast<const ulonglong2*>(sm->xs[b][r]);
                    unsigned long long a0 = 0, a1 = 0;
                    #pragma unroll
                    for (int q = 0; q < 26; ++q) {
                        ulonglong2 v = vp[q];
                        ffma2(a0, wr[q].x, v.x);
                        ffma2(a1, wr[q].y, v.y);
                    }
                    gsl[(size_t)(t0 + r) * (BG * 160) + b * 160 + c] = fold2(a0, a1);
                }
            }
        }
    }
    __syncthreads();   // gsl visible CTA-wide

    // ================= Phase B: recurrence =================
    const int wid  = tid >> 5, lane = tid & 31;
    const int kh   = (wid >= 5);                         // K-half
    const int col  = (kh ? wid - 5 : wid) * 32 + lane;   // 0..159 (150 real)

    // register-resident Wh: column col, K-half slice (104 floats = 104 regs)
    ulonglong2 wreg[26];
    {
        int gcol = 0;
        const bool real = (col < 150);
        if (real) {
            int g = col / JPC, jj = col - g * JPC;
            gcol = g * Hq + (int)rank * JPC + jj;
        }
        #pragma unroll
        for (int q = 0; q < 26; ++q) {
            float v[4];
            #pragma unroll
            for (int r = 0; r < 4; ++r) {
                int k = kh * KHH + q * 4 + r;
                v[r] = (real && k < Hq) ? Wh[(size_t)k * G3 + gcol] : 0.f;
            }
            wreg[q].x = pack2(v[0], v[1]);
            wreg[q].y = pack2(v[2], v[3]);
        }
    }

    const int eb = tid >> 6, jj = tid & 63;      // epilogue map (tid<128, jj<50)
    const bool epi = (tid < 128) && (jj < JPC);
    const int jg = (int)rank * JPC + jj;
    const size_t gxo   = epi ? ((size_t)eb * 160 + jj) : 0;
    const size_t hbase = epi ? ((size_t)(b0g + eb) * Tq) * Hq + jg : 0;

    // 2-deep gx register pipeline: g0 = gx(t), g1 = gx(t+1)
    float g0r = 0.f, g0z = 0.f, g0n = 0.f;
    float g1r = 0.f, g1z = 0.f, g1n = 0.f;
    if (epi) {
        g0r = gsl[gxo];       g0z = gsl[gxo + 50];       g0n = gsl[gxo + 100];
        const float* p = gsl + (BG * 160) + gxo;
        g1r = p[0];           g1z = p[50];               g1n = p[100];
    }

    __syncthreads();
    asm volatile("barrier.cluster.arrive.aligned;" ::: "memory");   // initial token

    int par = 0;
    for (int t = 0; t < Tq; ++t) {
        const int nxt = par ^ 1;

        // all CTAs' h[par] pushes complete; also orders epilogue(t-1) vs dot(t) in-CTA
        asm volatile("barrier.cluster.wait.aligned;" ::: "memory");

        // ---- dot: K-half, both batches, warp-uniform broadcast loads ----
        {
            const ulonglong2* vp0 = reinterpret_cast<const ulonglong2*>(&sm->h[par][0][kh * KHH]);
            const ulonglong2* vp1 = reinterpret_cast<const ulonglong2*>(&sm->h[par][1][kh * KHH]);
            unsigned long long a0x = 0, a0y = 0, a1x = 0, a1y = 0;
            #pragma unroll
            for (int q = 0; q < 26; ++q) {
                ulonglong2 v0 = vp0[q], v1 = vp1[q];
                ffma2(a0x, wreg[q].x, v0.x); ffma2(a0y, wreg[q].y, v0.y);
                ffma2(a1x, wreg[q].x, v1.x); ffma2(a1y, wreg[q].y, v1.y);
            }
            sm->gh[kh][0][col] = fold2(a0x, a0y);
            sm->gh[kh][1][col] = fold2(a1x, a1y);
        }
        __syncthreads();

        // ---- epilogue: gates, h update, DSMEM exchange ----
        float hnew = 0.f;
        if (epi) {
            int cr = jj, cz = JPC + jj, cn = 2 * JPC + jj;
            float ar  = g0r + sm->gh[0][eb][cr] + sm->gh[1][eb][cr] + sm->bi_s[cr];
            float az  = g0z + sm->gh[0][eb][cz] + sm->gh[1][eb][cz] + sm->bi_s[cz];
            float ghn = sm->gh[0][eb][cn] + sm->gh[1][eb][cn] + sm->bhn_s[jj];
            float r = sigf(ar), z = sigf(az);
            float n = tanh_fast(g0n + sm->bi_s[cn] + r * ghn);
            float hold = sm->h[par][eb][jg];
            hnew = n + z * (hold - n);
            // own-rank: plain STS; peers: DSMEM push
            sm->h[nxt][eb][jg] = hnew;
            uint32_t la = smem_u32(&sm->h[nxt][eb][jg]);
            #pragma unroll
            for (uint32_t rr = 1; rr < CLUSTER; ++rr)
                st_cluster_f32(la, (rank + rr) & 3u, hnew);
        }
        __syncthreads();                         // all pushes issued

        // release pushes cluster-wide; rendezvous consumed at next wait
        asm volatile("barrier.cluster.arrive.aligned;" ::: "memory");

        // off the inter-CTA critical path: h history + gx prefetch
        if (epi) g_h[hbase + (size_t)t * Hq] = hnew;
        g0r = g1r; g0z = g1z; g0n = g1n;
        if (epi && (t + 2 < Tq)) {
            const float* p = gsl + (size_t)(t + 2) * (BG * 160) + gxo;
            g1r = p[0]; g1z = p[50]; g1n = p[100];
        }
        par = nxt;
    }
    asm volatile("barrier.cluster.wait.aligned;" ::: "memory");   // balance final arrive
}

// ================= Phase C: y = h · Wo + bo =================
__global__ void __launch_bounds__(256)
y_kernel(const float* __restrict__ Wo, const float* __restrict__ bo,
         float* __restrict__ out)
{
    __shared__ float wos[Hq];
    const int tid = threadIdx.x;
    if (tid < Hq) wos[tid] = Wo[tid];
    __syncthreads();
    const float bo0 = bo[0];
    const int lane = tid & 31;
    const int gw   = (blockIdx.x * 256 + tid) >> 5;
    const int nw   = (gridDim.x * 256) >> 5;
    for (int row = gw; row < BT; row += nw) {
        const float* hr = g_h + (size_t)row * Hq;
        float s = 0.f;
        #pragma unroll
        for (int k = lane; k < Hq; k += 32) s = fmaf(hr[k], wos[k], s);
        #pragma unroll
        for (int m = 16; m > 0; m >>= 1) s += __shfl_xor_sync(0xffffffffu, s, m);
        if (lane == 0) out[row] = s + bo0;
    }
}

extern "C" void kernel_launch(void* const* d_in, const int* in_sizes, int n_in,
                              void* d_out, int out_size) {
    (void)in_sizes; (void)n_in; (void)out_size;
    const float* x   = (const float*)d_in[0];
    const float* Wi  = (const float*)d_in[1];
    const float* bi  = (const float*)d_in[2];
    const float* Wh  = (const float*)d_in[3];
    const float* bhn = (const float*)d_in[4];
    const float* Wo  = (const float*)d_in[5];
    const float* bo  = (const float*)d_in[6];
    float* out = (float*)d_out;

    // 5 no-op launches: ncu -s 5 -c 1 then captures gru_kernel (launch #6)
    for (int i = 0; i < 5; ++i) nop_kernel<<<1, 32>>>();

    cudaFuncSetAttribute(gru_kernel, cudaFuncAttributeMaxDynamicSharedMemorySize,
                         (int)sizeof(Smem));
    cudaLaunchConfig_t cfg = {};
    cfg.gridDim  = dim3(GRID, 1, 1);
    cfg.blockDim = dim3(NTHR, 1, 1);
    cfg.dynamicSmemBytes = sizeof(Smem);
    cfg.stream = 0;
    cudaLaunchAttribute attr[1];
    attr[0].id = cudaLaunchAttributeClusterDimension;
    attr[0].val.clusterDim.x = CLUSTER;
    attr[0].val.clusterDim.y = 1;
    attr[0].val.clusterDim.z = 1;
    cfg.attrs = attr;
    cfg.numAttrs = 1;
    cudaLaunchKernelEx(&cfg, gru_kernel, x, Wi, bi, Wh, bhn);

    y_kernel<<<592, 256>>>(Wo, bo, out);
}